// round 1
// baseline (speedup 1.0000x reference)
#include <cuda_runtime.h>
#include <cuda_bf16.h>

// Problem constants
#define NN 16384      // nodes/edges (and bond_n rows A = 16384)
#define DD 128        // emb dim
// Only layer i = 2 matters: the reference loop does not feed h back.

// Scratch (device globals — no allocation allowed)
__device__ float g_colw[NN];
__device__ float g_hn[(size_t)NN * DD];   // 8 MB
__device__ float g_m[DD];
__device__ float g_mm[DD];

// ---------------------------------------------------------------------------
// K0: zero the accumulators
// ---------------------------------------------------------------------------
__global__ void k0_zero() {
    int i = blockIdx.x * 256 + threadIdx.x;
    if (i < NN) g_colw[i] = 0.f;
    if (i < DD) g_m[i] = 0.f;
}

// ---------------------------------------------------------------------------
// K1: column sum of bond_n [16384, 16384]  ->  g_colw [16384]
// Grid = 16 column-tiles (1024 cols each) x 64 row-chunks (256 rows each)
// Coalesced float4 streaming loads (__ldcs: no reuse), per-column atomics.
// ---------------------------------------------------------------------------
__global__ void __launch_bounds__(256) k1_colsum(const float* __restrict__ bn) {
    int colTile  = blockIdx.x & 15;
    int rowChunk = blockIdx.x >> 4;
    int col = colTile * 1024 + threadIdx.x * 4;
    const float* base = bn + (size_t)rowChunk * 256 * NN + col;
    float ax = 0.f, ay = 0.f, az = 0.f, aw = 0.f;
#pragma unroll 8
    for (int r = 0; r < 256; r++) {
        float4 v = __ldcs((const float4*)(base + (size_t)r * NN));
        ax += v.x; ay += v.y; az += v.z; aw += v.w;
    }
    atomicAdd(&g_colw[col + 0], ax);
    atomicAdd(&g_colw[col + 1], ay);
    atomicAdd(&g_colw[col + 2], az);
    atomicAdd(&g_colw[col + 3], aw);
}

// ---------------------------------------------------------------------------
// K2: h_n = relu(cat @ Wi_w[2].T + Wi_b[2])   [16384 x 128], K = 256
//     + fused partial reduction m[d] += col_w[n] * h_n[n,d]
// 128 blocks x 256 threads; each block does 128 rows.
// W^T staged in smem as w_s[256][129] (pad -> conflict-free fill & read).
// cat staged per 64-k chunk as cat_s[128][64] (built from embedding gathers).
// Thread tile: 8 rows (r = ty + 16*i) x 8 cols (d = tx + 16*j).
// ---------------------------------------------------------------------------
__global__ void __launch_bounds__(256) k2_gemm(
    const int* __restrict__ x, const int* __restrict__ ea,
    const float* __restrict__ aemb, const float* __restrict__ bemb,
    const float* __restrict__ Wi_w2, const float* __restrict__ Wi_b2)
{
    extern __shared__ float sm[];
    float* w_s   = sm;                 // [256][129] = 132,096 B
    float* cat_s = sm + 256 * 129;     // [128][64]  =  32,768 B

    __shared__ float bias_s[128], colw_s[128], m_s[128];
    __shared__ int xi0[128], xi1[128], ei0[128], ei1[128];

    int tid = threadIdx.x;
    int rowBase = blockIdx.x * 128;

    // Stage W transposed: w_s[k][d] = Wi_w2[d*256 + k]
    // (global reads coalesced over k; smem stride 129 -> conflict-free stores)
    for (int idx = tid; idx < 32768; idx += 256) {
        int d = idx >> 8, k = idx & 255;
        w_s[k * 129 + d] = Wi_w2[idx];
    }
    if (tid < 128) {
        bias_s[tid] = Wi_b2[tid];
        colw_s[tid] = g_colw[rowBase + tid];
        m_s[tid]    = 0.f;
        int r = rowBase + tid;
        xi0[tid] = x[2 * r];  xi1[tid] = x[2 * r + 1];
        ei0[tid] = ea[2 * r]; ei1[tid] = ea[2 * r + 1];
    }
    __syncthreads();

    int tx = tid & 15, ty = tid >> 4;
    float acc[8][8];
#pragma unroll
    for (int i = 0; i < 8; i++)
#pragma unroll
        for (int j = 0; j < 8; j++) acc[i][j] = 0.f;

    for (int kc = 0; kc < 256; kc += 64) {
        const bool atom = (kc < 128);
        const float* emb = atom ? aemb : bemb;
        // Fill cat tile: 2048 float4 elements; lanes sweep k for a row -> coalesced gathers
        for (int idx = tid; idx < 2048; idx += 256) {
            int row  = idx >> 4;
            int kloc = (idx & 15) * 4;
            int i0 = atom ? xi0[row] : ei0[row];
            int i1 = atom ? xi1[row] : ei1[row];
            int ko = atom ? (kc + kloc) : (kc - 128 + kloc);
            float4 v0 = *(const float4*)(emb + i0 * 128 + ko);
            float4 v1 = *(const float4*)(emb + i1 * 128 + ko);
            float4 s;
            s.x = v0.x + v1.x; s.y = v0.y + v1.y;
            s.z = v0.z + v1.z; s.w = v0.w + v1.w;
            *(float4*)(cat_s + row * 64 + kloc) = s;
        }
        __syncthreads();

#pragma unroll 8
        for (int kk = 0; kk < 64; kk++) {
            const float* wr = w_s + (size_t)(kc + kk) * 129;  // uniform per iter
            float b[8], a[8];
#pragma unroll
            for (int j = 0; j < 8; j++) b[j] = wr[tx + 16 * j];
#pragma unroll
            for (int i = 0; i < 8; i++) a[i] = cat_s[(ty + 16 * i) * 64 + kk];
#pragma unroll
            for (int i = 0; i < 8; i++)
#pragma unroll
                for (int j = 0; j < 8; j++)
                    acc[i][j] = fmaf(a[i], b[j], acc[i][j]);
        }
        __syncthreads();
    }

    // Epilogue: bias + relu, store h_n, fold weighted row-sum into m
    float p[8];
#pragma unroll
    for (int j = 0; j < 8; j++) p[j] = 0.f;
#pragma unroll
    for (int i = 0; i < 8; i++) {
        int r = ty + 16 * i;
        float cw = colw_s[r];
#pragma unroll
        for (int j = 0; j < 8; j++) {
            int d = tx + 16 * j;
            float v = acc[i][j] + bias_s[d];
            v = v > 0.f ? v : 0.f;
            g_hn[(size_t)(rowBase + r) * 128 + d] = v;
            p[j] += cw * v;
        }
    }
#pragma unroll
    for (int j = 0; j < 8; j++) atomicAdd(&m_s[tx + 16 * j], p[j]);
    __syncthreads();
    if (tid < 128) atomicAdd(&g_m[tid], m_s[tid]);
}

// ---------------------------------------------------------------------------
// K3: mm[d] = Wm_b2[d] + sum_k m[k] * Wm_w2[d,k]   (tiny, 1 block)
// ---------------------------------------------------------------------------
__global__ void k3_mm(const float* __restrict__ Wm_w2,
                      const float* __restrict__ Wm_b2) {
    __shared__ float ms[128];
    int d = threadIdx.x;
    ms[d] = g_m[d];
    __syncthreads();
    float s = Wm_b2[d];
    const float* row = Wm_w2 + d * 128;
#pragma unroll 8
    for (int k = 0; k < 128; k++) s = fmaf(ms[k], __ldg(row + k), s);
    g_mm[d] = s;
}

// ---------------------------------------------------------------------------
// K4: out = relu(h_n + mm[broadcast])   (16 MB traffic, float4)
// ---------------------------------------------------------------------------
__global__ void __launch_bounds__(256) k4_out(float* __restrict__ out) {
    __shared__ float mm[128];
    if (threadIdx.x < 128) mm[threadIdx.x] = g_mm[threadIdx.x];
    __syncthreads();
    size_t i = (size_t)blockIdx.x * 256 + threadIdx.x;   // float4 index
    float4 v = *(const float4*)(g_hn + i * 4);
    int d0 = (int)((i * 4) & 127);
    v.x = fmaxf(v.x + mm[d0 + 0], 0.f);
    v.y = fmaxf(v.y + mm[d0 + 1], 0.f);
    v.z = fmaxf(v.z + mm[d0 + 2], 0.f);
    v.w = fmaxf(v.w + mm[d0 + 3], 0.f);
    *((float4*)out + i) = v;
}

// ---------------------------------------------------------------------------
extern "C" void kernel_launch(void* const* d_in, const int* in_sizes, int n_in,
                              void* d_out, int out_size) {
    const int*   x    = (const int*)d_in[0];
    const int*   ea   = (const int*)d_in[1];
    const float* bn   = (const float*)d_in[2];
    const float* aemb = (const float*)d_in[3];
    const float* bemb = (const float*)d_in[4];
    const float* Wi_w = (const float*)d_in[5];
    const float* Wi_b = (const float*)d_in[6];
    const float* Wm_w = (const float*)d_in[7];
    const float* Wm_b = (const float*)d_in[8];

    // Only the last layer (i = 2) affects the output.
    const float* Wi_w2 = Wi_w + 2 * 128 * 256;
    const float* Wi_b2 = Wi_b + 2 * 128;
    const float* Wm_w2 = Wm_w + 2 * 128 * 128;
    const float* Wm_b2 = Wm_b + 2 * 128;

    const int smem_k2 = (256 * 129 + 128 * 64) * (int)sizeof(float); // 164,864 B
    cudaFuncSetAttribute(k2_gemm, cudaFuncAttributeMaxDynamicSharedMemorySize, smem_k2);

    k0_zero<<<64, 256>>>();
    k1_colsum<<<1024, 256>>>(bn);
    k2_gemm<<<128, 256, smem_k2>>>(x, ea, aemb, bemb, Wi_w2, Wi_b2);
    k3_mm<<<1, 128>>>(Wm_w2, Wm_b2);
    k4_out<<<2048, 256>>>((float*)d_out);
}

// round 2
// speedup vs baseline: 1.3375x; 1.3375x over previous
#include <cuda_runtime.h>
#include <cuda_bf16.h>

#define NN 16384      // nodes/edges (and bond_n rows A = 16384)
#define DD 128        // emb dim
// Only layer i = 2 matters: the reference loop does not feed h back.

// Scratch (device globals — zero-initialized at module load)
__device__ float g_colw[NN];
__device__ float g_hn[(size_t)NN * DD];      // 8 MB
__device__ float g_mpart[128][DD];           // per-block partials of m
__device__ float g_mm[DD];
__device__ unsigned g_cnt;                   // last-block counter (self-resetting)

// ---------------------------------------------------------------------------
// FUSED kernel: block-specialized.
//   blocks [0,128):   column-sum of bond_n. Block b owns columns
//                     [b*128, b*128+128) over ALL 16384 rows -> g_colw (no atomics).
//   blocks [128,256): GEMM h_n = relu(cat @ Wi_w[2].T + b), 128 rows per block.
// Both run concurrently in wave 1; GEMM compute hides under the 1 GB stream.
// ---------------------------------------------------------------------------
__global__ void __launch_bounds__(256) k_fused(
    const float* __restrict__ bn,
    const int* __restrict__ x, const int* __restrict__ ea,
    const float* __restrict__ aemb, const float* __restrict__ bemb,
    const float* __restrict__ Wi_w2, const float* __restrict__ Wi_b2)
{
    extern __shared__ float sm[];
    const int tid = threadIdx.x;
    const int bid = blockIdx.x;

    if (bid < 128) {
        // ---------------- column-sum path ----------------
        const int lane = tid & 31, warp = tid >> 5;
        // each thread: 4 columns, rows warp, warp+8, ... (2048 rows)
        const float* base = bn + (size_t)warp * NN + bid * 128 + lane * 4;
        float4 a0 = {0,0,0,0}, a1 = {0,0,0,0}, a2 = {0,0,0,0}, a3 = {0,0,0,0};
        for (int i = 0; i < 2048; i += 16) {
#pragma unroll
            for (int u = 0; u < 16; u++) {
                float4 v = __ldcs((const float4*)(base + (size_t)(i + u) * 8 * NN));
                float4& a = (u & 3) == 0 ? a0 : (u & 3) == 1 ? a1 : (u & 3) == 2 ? a2 : a3;
                a.x += v.x; a.y += v.y; a.z += v.z; a.w += v.w;
            }
        }
        float sx = a0.x + a1.x + a2.x + a3.x;
        float sy = a0.y + a1.y + a2.y + a3.y;
        float sz = a0.z + a1.z + a2.z + a3.z;
        float sw = a0.w + a1.w + a2.w + a3.w;
        // cross-warp reduce: part[8][128]
        float* part = sm;
        part[warp * 128 + lane * 4 + 0] = sx;
        part[warp * 128 + lane * 4 + 1] = sy;
        part[warp * 128 + lane * 4 + 2] = sz;
        part[warp * 128 + lane * 4 + 3] = sw;
        __syncthreads();
        if (tid < 128) {
            float s = 0.f;
#pragma unroll
            for (int w = 0; w < 8; w++) s += part[w * 128 + tid];
            g_colw[bid * 128 + tid] = s;
        }
        return;
    }

    // ---------------- GEMM path ----------------
    float* w_s   = sm;                 // [64][129]  = 33,024 B (per-k chunk)
    float* cat_s = sm + 64 * 129;      // [128][64]  = 32,768 B

    __shared__ float bias_s[128];
    __shared__ int xi0[128], xi1[128], ei0[128], ei1[128];

    const int rowBase = (bid - 128) * 128;

    if (tid < 128) {
        bias_s[tid] = Wi_b2[tid];
        int r = rowBase + tid;
        xi0[tid] = x[2 * r];  xi1[tid] = x[2 * r + 1];
        ei0[tid] = ea[2 * r]; ei1[tid] = ea[2 * r + 1];
    }
    __syncthreads();

    const int tx = tid & 15, ty = tid >> 4;
    float acc[8][8];
#pragma unroll
    for (int i = 0; i < 8; i++)
#pragma unroll
        for (int j = 0; j < 8; j++) acc[i][j] = 0.f;

    for (int kc = 0; kc < 256; kc += 64) {
        // stage W chunk transposed: w_s[kk][d] = Wi_w2[d*256 + kc + kk]
        for (int idx = tid; idx < 8192; idx += 256) {
            int d = idx >> 6, kk = idx & 63;
            w_s[kk * 129 + d] = Wi_w2[d * 256 + kc + kk];
        }
        // stage cat chunk: cat_s[row][kloc] (embedding pair-sum gathers)
        const bool atom = (kc < 128);
        const float* emb = atom ? aemb : bemb;
        for (int idx = tid; idx < 2048; idx += 256) {
            int row  = idx >> 4;
            int kloc = (idx & 15) * 4;
            int i0 = atom ? xi0[row] : ei0[row];
            int i1 = atom ? xi1[row] : ei1[row];
            int ko = atom ? (kc + kloc) : (kc - 128 + kloc);
            float4 v0 = *(const float4*)(emb + i0 * 128 + ko);
            float4 v1 = *(const float4*)(emb + i1 * 128 + ko);
            float4 s;
            s.x = v0.x + v1.x; s.y = v0.y + v1.y;
            s.z = v0.z + v1.z; s.w = v0.w + v1.w;
            *(float4*)(cat_s + row * 64 + kloc) = s;
        }
        __syncthreads();

#pragma unroll 8
        for (int kk = 0; kk < 64; kk++) {
            const float* wr = w_s + kk * 129;
            float b[8], a[8];
#pragma unroll
            for (int j = 0; j < 8; j++) b[j] = wr[tx + 16 * j];
#pragma unroll
            for (int i = 0; i < 8; i++) a[i] = cat_s[(ty + 16 * i) * 64 + kk];
#pragma unroll
            for (int i = 0; i < 8; i++)
#pragma unroll
                for (int j = 0; j < 8; j++)
                    acc[i][j] = fmaf(a[i], b[j], acc[i][j]);
        }
        __syncthreads();
    }

    // epilogue: bias + relu -> g_hn
#pragma unroll
    for (int i = 0; i < 8; i++) {
        int r = ty + 16 * i;
#pragma unroll
        for (int j = 0; j < 8; j++) {
            int d = tx + 16 * j;
            float v = acc[i][j] + bias_s[d];
            g_hn[(size_t)(rowBase + r) * 128 + d] = v > 0.f ? v : 0.f;
        }
    }
}

// ---------------------------------------------------------------------------
// k_m: m[d] = sum_n colw[n]*h_n[n,d], partials per block (no atomics),
//      then the LAST block reduces partials and computes
//      mm = m @ Wm_w2.T + Wm_b2. Counter self-resets for graph replay.
// ---------------------------------------------------------------------------
__global__ void __launch_bounds__(256) k_m(const float* __restrict__ Wm_w2,
                                           const float* __restrict__ Wm_b2) {
    __shared__ float red[256];
    __shared__ float ms[128];
    __shared__ bool last;

    const int b = blockIdx.x, tid = threadIdx.x;
    const int d = tid & 127, half = tid >> 7;
    const int rowBase = b * 128 + half * 64;

    float p = 0.f;
#pragma unroll 4
    for (int r = 0; r < 64; r++) {
        int row = rowBase + r;
        p = fmaf(g_colw[row], g_hn[(size_t)row * DD + d], p);
    }
    red[tid] = p;
    __syncthreads();
    if (tid < 128) g_mpart[b][tid] = red[tid] + red[tid + 128];
    __threadfence();
    if (tid == 0) last = (atomicAdd(&g_cnt, 1u) == 127u);
    __syncthreads();

    if (last) {
        if (tid < 128) {
            float s = 0.f;
#pragma unroll 8
            for (int w = 0; w < 128; w++) s += __ldcg(&g_mpart[w][tid]);
            ms[tid] = s;
        }
        __syncthreads();
        if (tid < 128) {
            float s = Wm_b2[tid];
            const float* row = Wm_w2 + tid * 128;
#pragma unroll 8
            for (int k = 0; k < 128; k++) s = fmaf(ms[k], __ldg(row + k), s);
            g_mm[tid] = s;
        }
        if (tid == 0) g_cnt = 0u;   // reset for next graph replay
    }
}

// ---------------------------------------------------------------------------
// k_out: out = relu(h_n + mm[broadcast])
// ---------------------------------------------------------------------------
__global__ void __launch_bounds__(256) k_out(float* __restrict__ out) {
    __shared__ float mm[128];
    if (threadIdx.x < 128) mm[threadIdx.x] = g_mm[threadIdx.x];
    __syncthreads();
    size_t i = (size_t)blockIdx.x * 256 + threadIdx.x;   // float4 index
    float4 v = *(const float4*)(g_hn + i * 4);
    int d0 = (int)((i * 4) & 127);
    v.x = fmaxf(v.x + mm[d0 + 0], 0.f);
    v.y = fmaxf(v.y + mm[d0 + 1], 0.f);
    v.z = fmaxf(v.z + mm[d0 + 2], 0.f);
    v.w = fmaxf(v.w + mm[d0 + 3], 0.f);
    *((float4*)out + i) = v;
}

// ---------------------------------------------------------------------------
extern "C" void kernel_launch(void* const* d_in, const int* in_sizes, int n_in,
                              void* d_out, int out_size) {
    const int*   x    = (const int*)d_in[0];
    const int*   ea   = (const int*)d_in[1];
    const float* bn   = (const float*)d_in[2];
    const float* aemb = (const float*)d_in[3];
    const float* bemb = (const float*)d_in[4];
    const float* Wi_w = (const float*)d_in[5];
    const float* Wi_b = (const float*)d_in[6];
    const float* Wm_w = (const float*)d_in[7];
    const float* Wm_b = (const float*)d_in[8];

    // Only the last layer (i = 2) affects the output.
    const float* Wi_w2 = Wi_w + 2 * 128 * 256;
    const float* Wi_b2 = Wi_b + 2 * 128;
    const float* Wm_w2 = Wm_w + 2 * 128 * 128;
    const float* Wm_b2 = Wm_b + 2 * 128;

    const int smem = (64 * 129 + 128 * 64) * (int)sizeof(float);  // 65,792 B
    static bool attr_set = false;
    if (!attr_set) {
        cudaFuncSetAttribute(k_fused, cudaFuncAttributeMaxDynamicSharedMemorySize, smem);
        attr_set = true;
    }

    k_fused<<<256, 256, smem>>>(bn, x, ea, aemb, bemb, Wi_w2, Wi_b2);
    k_m<<<128, 256>>>(Wm_w2, Wm_b2);
    k_out<<<2048, 256>>>((float*)d_out);
}